// round 16
// baseline (speedup 1.0000x reference)
#include <cuda_runtime.h>
#include <cuda_fp16.h>
#include <cstdint>

#define NB 8
#define SEQ 2048
#define DIN 512
#define DH 128
#define MTOT (NB*SEQ)

// Scratch (device globals: allocation-free rule)
__device__ __half h_q[MTOT*DH];   // [b][s][dh], pre-scaled by 1/sqrt(DH)
__device__ __half h_k[MTOT*DH];   // [b][s][dh]
__device__ __half h_v[MTOT*DH];   // TRANSPOSED: [b][dh][s]
__device__ __half h_wt[3*DH*DIN]; // W fp16, transposed: [sel][n][k]

// ---------------------------------------------------------------------------
// helpers (baseline sm_75/sm_80 ISA only)
// ---------------------------------------------------------------------------
__device__ __forceinline__ uint32_t smem_u32(const void* p) {
    uint32_t a;
    asm("{ .reg .u64 t; cvta.to.shared.u64 t, %1; cvt.u32.u64 %0, t; }" : "=r"(a) : "l"(p));
    return a;
}
// pack two fp32 -> fp16x2 (lo = first arg)
__device__ __forceinline__ uint32_t f2h2(float lo, float hi) {
    uint32_t r;
    asm("cvt.rn.f16x2.f32 %0, %1, %2;" : "=r"(r) : "f"(hi), "f"(lo));
    return r;
}
__device__ __forceinline__ void mma16(float* c, const uint32_t* a, const uint32_t* b) {
    asm volatile(
        "mma.sync.aligned.m16n8k16.row.col.f32.f16.f16.f32 "
        "{%0,%1,%2,%3}, {%4,%5,%6,%7}, {%8,%9}, {%0,%1,%2,%3};"
        : "+f"(c[0]), "+f"(c[1]), "+f"(c[2]), "+f"(c[3])
        : "r"(a[0]), "r"(a[1]), "r"(a[2]), "r"(a[3]), "r"(b[0]), "r"(b[1]));
}
__device__ __forceinline__ void ldsm4(uint32_t* r, uint32_t addr) {
    asm volatile("ldmatrix.sync.aligned.m8n8.x4.shared.b16 {%0,%1,%2,%3}, [%4];"
        : "=r"(r[0]), "=r"(r[1]), "=r"(r[2]), "=r"(r[3]) : "r"(addr));
}
__device__ __forceinline__ void cp16(void* dst, const void* src) {
    uint32_t d;
    asm("{ .reg .u64 t; cvta.to.shared.u64 t, %1; cvt.u32.u64 %0, t; }" : "=r"(d) : "l"(dst));
    asm volatile("cp.async.cg.shared.global [%0], [%1], 16;" :: "r"(d), "l"(src));
}
#define CP_COMMIT() asm volatile("cp.async.commit_group;" ::: "memory")
#define CP_WAIT1()  asm volatile("cp.async.wait_group 1;" ::: "memory")
#define CP_WAIT0()  asm volatile("cp.async.wait_group 0;" ::: "memory")

// ===========================================================================
// wprep: round W to fp16 and transpose into h_wt[sel][n][k].
// ===========================================================================
__global__ __launch_bounds__(256) void wprep_kernel(
    const float* __restrict__ w0, const float* __restrict__ w1, const float* __restrict__ w2)
{
    int sel = blockIdx.y;
    const float* W  = sel == 0 ? w0 : (sel == 1 ? w1 : w2);
    __half*      Wt = h_wt + (size_t)sel * DH * DIN;
    int idx = blockIdx.x * 256 + threadIdx.x;
    int k = idx >> 5, n4 = (idx & 31) * 4;
    float4 v = *(const float4*)(W + (size_t)k * DH + n4);
    Wt[(size_t)(n4 + 0) * DIN + k] = __float2half_rn(v.x);
    Wt[(size_t)(n4 + 1) * DIN + k] = __float2half_rn(v.y);
    Wt[(size_t)(n4 + 2) * DIN + k] = __float2half_rn(v.z);
    Wt[(size_t)(n4 + 3) * DIN + k] = __float2half_rn(v.w);
}

// ===========================================================================
// proj fp16: Out = X*W + bias, fp16 operands (fp32 accum), fp16 outputs.
// BM=128, BN=128, BK=32 (2 k16-steps), 16 stages.  8 warps 4(m) x 2(n).
// X: fp32 LDG -> f2h2 -> fp16 smem (double buffer).  W: fp16 cp.async.
// Smem (u32 words, all rows stride 20 = 32 fp16 + pad):
//   Xs[2] @0, @2560 ;  Ws[2] @5120, @7680.  Total 10240 w = 40960 B.
// q pre-scaled by 1/sqrt(DH).  V written TRANSPOSED fp16 [b][dh][s].
// ===========================================================================
#define PJ_SMEM (10240 * 4)

__global__ __launch_bounds__(256, 2) void proj_kernel(
    const float* __restrict__ x0, const float* __restrict__ x1, const float* __restrict__ x2,
    const float* __restrict__ b0, const float* __restrict__ b1, const float* __restrict__ b2)
{
    extern __shared__ uint32_t ds[];
    uint32_t sb = smem_u32(ds);

    int sel = blockIdx.y;
    const float* X    = sel == 0 ? x0 : (sel == 1 ? x1 : x2);
    const float* bias = sel == 0 ? b0 : (sel == 1 ? b1 : b2);
    const __half* Wt  = h_wt + (size_t)sel * DH * DIN;

    int m0  = blockIdx.x * 128;
    int tid = threadIdx.x;
    int lane = tid & 31, wid = tid >> 5;
    int wm = wid & 3, wn = wid >> 2;
    int g = lane >> 2, t = lane & 3;

    // ldsm per-lane bases (flash-validated patterns)
    int rA  = lane & 15;                                // A: rows 0-15
    int kwA = (lane & 16) ? 4 : 0;                      //    k-half word
    int rB  = (lane & 7) + ((lane & 16) ? 8 : 0);       // B: n-rows
    int kwB = (lane & 8) ? 4 : 0;

    // X copy slots: thread -> row tid>>1, half (16 floats) tid&1
    int xr = tid >> 1, xh = tid & 1;
    const float* Xrow = X + (size_t)(m0 + xr) * DIN + xh * 16;
    uint32_t xs_base = (uint32_t)(xr * 20 + xh * 8);

    float acc[2][8][4];
    #pragma unroll
    for (int i = 0; i < 2; i++)
        #pragma unroll
        for (int j = 0; j < 8; j++)
            #pragma unroll
            for (int q = 0; q < 4; q++) acc[i][j][q] = 0.f;

    // ---- prologue: stage 0 ----
    {
        float4 x4[4];
        #pragma unroll
        for (int j = 0; j < 4; j++) x4[j] = *(const float4*)(Xrow + j * 4);
        #pragma unroll
        for (int j = 0; j < 4; j += 2) {
            uint4 u = { f2h2(x4[j].x, x4[j].y),   f2h2(x4[j].z, x4[j].w),
                        f2h2(x4[j+1].x, x4[j+1].y), f2h2(x4[j+1].z, x4[j+1].w) };
            *(uint4*)&ds[xs_base + j * 2] = u;
        }
        #pragma unroll
        for (int it = 0; it < 2; it++) {
            int idx = tid + it * 256, r = idx >> 2, c = idx & 3;
            cp16(&ds[5120 + r * 20 + c * 4], Wt + (size_t)r * DIN + c * 8);
        }
        CP_COMMIT();
    }

    for (int i = 0; i < 16; i++) {
        int cur = i & 1;
        if (i < 15) {
            int k1 = (i + 1) * 32;
            // next X -> regs -> other Xs buffer (no hazard: other buffer)
            float4 x4[4];
            #pragma unroll
            for (int j = 0; j < 4; j++) x4[j] = *(const float4*)(Xrow + k1 + j * 4);
            uint32_t* Xn = ds + (cur ^ 1) * 2560;
            #pragma unroll
            for (int j = 0; j < 4; j += 2) {
                uint4 u = { f2h2(x4[j].x, x4[j].y),   f2h2(x4[j].z, x4[j].w),
                            f2h2(x4[j+1].x, x4[j+1].y), f2h2(x4[j+1].z, x4[j+1].w) };
                *(uint4*)&Xn[xs_base + j * 2] = u;
            }
            // next W -> other Ws buffer
            uint32_t* Wn = ds + 5120 + (cur ^ 1) * 2560;
            #pragma unroll
            for (int it = 0; it < 2; it++) {
                int idx = tid + it * 256, r = idx >> 2, c = idx & 3;
                cp16(&Wn[r * 20 + c * 4], Wt + (size_t)r * DIN + k1 + c * 8);
            }
            CP_COMMIT();
            CP_WAIT1();
        } else {
            CP_WAIT0();
        }
        __syncthreads();   // X(i), W(i) visible

        uint32_t Xb = sb + ((cur * 2560) << 2);
        uint32_t Wb = sb + ((5120 + cur * 2560) << 2);

        // A-frags: 2 mt x 2 k16-steps
        uint32_t af[2][2][4];
        #pragma unroll
        for (int mt = 0; mt < 2; mt++)
            #pragma unroll
            for (int ks = 0; ks < 2; ks++)
                ldsm4(af[mt][ks], Xb + (((wm * 32 + mt * 16 + rA) * 20 + ks * 8 + kwA) << 2));
        // B-frags + MMAs per k16-step
        #pragma unroll
        for (int ks = 0; ks < 2; ks++) {
            uint32_t bf[4][4];
            #pragma unroll
            for (int p = 0; p < 4; p++)
                ldsm4(bf[p], Wb + (((wn * 64 + p * 16 + rB) * 20 + ks * 8 + kwB) << 2));
            #pragma unroll
            for (int mt = 0; mt < 2; mt++)
                #pragma unroll
                for (int nt = 0; nt < 8; nt++)
                    mma16(acc[mt][nt], af[mt][ks], &bf[nt >> 1][(nt & 1) * 2]);
        }
        __syncthreads();   // all reads done before next stage's writes
    }

    const float qscale = 0.08838834764831845f;  // 1/sqrt(128), folded into q
    #pragma unroll
    for (int mt = 0; mt < 2; mt++) {
        int m = m0 + wm * 32 + mt * 16 + g;
        if (sel != 2) {
            __half* Out = sel == 0 ? h_q : h_k;
            float sc = sel == 0 ? qscale : 1.0f;
            #pragma unroll
            for (int nt = 0; nt < 8; nt++) {
                int col = wn * 64 + nt * 8 + 2 * t;
                float bb0 = bias[col], bb1 = bias[col + 1];
                uint32_t lo = f2h2((acc[mt][nt][0] + bb0) * sc, (acc[mt][nt][1] + bb1) * sc);
                uint32_t hi = f2h2((acc[mt][nt][2] + bb0) * sc, (acc[mt][nt][3] + bb1) * sc);
                *(uint32_t*)(Out + (size_t)m * DH + col)       = lo;
                *(uint32_t*)(Out + (size_t)(m + 8) * DH + col) = hi;
            }
        } else {
            int b = m >> 11, s = m & 2047;
            __half* Vb = h_v + (size_t)b * DH * SEQ;
            #pragma unroll
            for (int nt = 0; nt < 8; nt++) {
                int col = wn * 64 + nt * 8 + 2 * t;
                float bb0 = bias[col], bb1 = bias[col + 1];
                Vb[(size_t)col * SEQ + s]           = __float2half_rn(acc[mt][nt][0] + bb0);
                Vb[(size_t)(col + 1) * SEQ + s]     = __float2half_rn(acc[mt][nt][1] + bb1);
                Vb[(size_t)col * SEQ + s + 8]       = __float2half_rn(acc[mt][nt][2] + bb0);
                Vb[(size_t)(col + 1) * SEQ + s + 8] = __float2half_rn(acc[mt][nt][3] + bb1);
            }
        }
    }
}

// ===========================================================================
// Flash attention, fp16 (m16n8k16) — UNCHANGED from round 15 (measured best).
// ===========================================================================
#define FL_SMEM (9472 * 4)

__global__ __launch_bounds__(128, 3) void flash_kernel(float* __restrict__ Out)
{
    extern __shared__ uint32_t ds[];
    uint32_t sb = smem_u32(ds);

    int b  = blockIdx.y;
    int m0 = blockIdx.x * 64;
    const __half* Qg = h_q + (size_t)b * SEQ * DH + (size_t)m0 * DH;
    const __half* Kg = h_k + (size_t)b * SEQ * DH;
    const __half* Vt = h_v + (size_t)b * DH * SEQ;
    float*        Ob = Out + (size_t)b * SEQ * DH + (size_t)m0 * DH;

    int tid = threadIdx.x, lane = tid & 31, wq = tid >> 5;
    int g = lane >> 2, t = lane & 3;

    #pragma unroll
    for (int it = 0; it < 8; it++) {
        int idx = tid + it * 128, r = idx >> 4, c = idx & 15;
        cp16(&ds[r * 68 + c * 4], Qg + (size_t)r * DH + c * 8);
    }
    CP_COMMIT(); CP_WAIT0(); __syncthreads();

    int rA  = (lane & 7) + ((lane & 8) ? 8 : 0);
    int kwA = (lane & 16) ? 4 : 0;
    uint32_t qa = sb + (((wq * 16 + rA) * 68 + kwA) << 2);
    uint32_t q[8][4];
    #pragma unroll
    for (int ks = 0; ks < 8; ks++) ldsm4(q[ks], qa + ks * 32);
    __syncthreads();

    #pragma unroll
    for (int it = 0; it < 4; it++) {
        int idx = tid + it * 128, r = idx >> 4, c = idx & 15;
        cp16(&ds[r * 68 + c * 4], Kg + (size_t)r * DH + c * 8);
    }
    #pragma unroll
    for (int it = 0; it < 4; it++) {
        int idx = tid + it * 128, r = idx >> 2, c = idx & 3;
        cp16(&ds[4352 + r * 20 + c * 4], Vt + (size_t)r * SEQ + c * 8);
    }
    CP_COMMIT();

    int rB  = (lane & 7) + ((lane & 16) ? 8 : 0);
    int kwB = (lane & 8) ? 4 : 0;
    uint32_t kb_off = (uint32_t)(rB * 68 + kwB);
    uint32_t vb_off = (uint32_t)(rB * 20 + kwB);

    float m0r = -1e30f, m1r = -1e30f, l0 = 0.f, l1 = 0.f;
    float o[16][4];
    #pragma unroll
    for (int i = 0; i < 16; i++)
        #pragma unroll
        for (int qd = 0; qd < 4; qd++) o[i][qd] = 0.f;

    for (int i = 0; i < SEQ / 32; i++) {
        int cur = i & 1;
        CP_WAIT0();
        __syncthreads();

        if (i < SEQ / 32 - 1) {
            int k1 = (i + 1) * 32;
            uint32_t* Kn = ds + (cur ^ 1) * 2176;
            uint32_t* Vn = ds + 4352 + (cur ^ 1) * 2560;
            #pragma unroll
            for (int it = 0; it < 4; it++) {
                int idx = tid + it * 128, r = idx >> 4, c = idx & 15;
                cp16(&Kn[r * 68 + c * 4], Kg + (size_t)(k1 + r) * DH + c * 8);
            }
            #pragma unroll
            for (int it = 0; it < 4; it++) {
                int idx = tid + it * 128, r = idx >> 2, c = idx & 3;
                cp16(&Vn[r * 20 + c * 4], Vt + (size_t)r * SEQ + k1 + c * 8);
            }
            CP_COMMIT();
        }

        uint32_t Kb = sb + ((cur * 2176) << 2);
        uint32_t Vb = sb + ((4352 + cur * 2560) << 2);

        float s_[4][4];
        #pragma unroll
        for (int j = 0; j < 4; j++)
            #pragma unroll
            for (int qd = 0; qd < 4; qd++) s_[j][qd] = 0.f;

        #pragma unroll
        for (int ks = 0; ks < 8; ks++) {
            uint32_t B0[4], B1[4];
            ldsm4(B0, Kb + ((kb_off + ks * 8) << 2));
            ldsm4(B1, Kb + ((kb_off + 1088 + ks * 8) << 2));
            mma16(s_[0], q[ks], B0);
            mma16(s_[1], q[ks], B0 + 2);
            mma16(s_[2], q[ks], B1);
            mma16(s_[3], q[ks], B1 + 2);
        }

        float mx0 = -1e30f, mx1 = -1e30f;
        #pragma unroll
        for (int j = 0; j < 4; j++) {
            mx0 = fmaxf(mx0, fmaxf(s_[j][0], s_[j][1]));
            mx1 = fmaxf(mx1, fmaxf(s_[j][2], s_[j][3]));
        }
        mx0 = fmaxf(mx0, __shfl_xor_sync(0xffffffffu, mx0, 1));
        mx0 = fmaxf(mx0, __shfl_xor_sync(0xffffffffu, mx0, 2));
        mx1 = fmaxf(mx1, __shfl_xor_sync(0xffffffffu, mx1, 1));
        mx1 = fmaxf(mx1, __shfl_xor_sync(0xffffffffu, mx1, 2));

        float mn0 = fmaxf(m0r, mx0), mn1 = fmaxf(m1r, mx1);
        float sc0 = __expf(m0r - mn0), sc1 = __expf(m1r - mn1);
        m0r = mn0; m1r = mn1;

        uint32_t pA[2][4];
        float ts0 = 0.f, ts1 = 0.f;
        #pragma unroll
        for (int j = 0; j < 4; j++) {
            float e0 = __expf(s_[j][0] - mn0);
            float e1 = __expf(s_[j][1] - mn0);
            float e2 = __expf(s_[j][2] - mn1);
            float e3 = __expf(s_[j][3] - mn1);
            ts0 += e0 + e1; ts1 += e2 + e3;
            pA[j >> 1][(j & 1) * 2 + 0] = f2h2(e0, e1);
            pA[j >> 1][(j & 1) * 2 + 1] = f2h2(e2, e3);
        }
        ts0 += __shfl_xor_sync(0xffffffffu, ts0, 1);
        ts0 += __shfl_xor_sync(0xffffffffu, ts0, 2);
        ts1 += __shfl_xor_sync(0xffffffffu, ts1, 1);
        ts1 += __shfl_xor_sync(0xffffffffu, ts1, 2);
        l0 = l0 * sc0 + ts0;
        l1 = l1 * sc1 + ts1;

        #pragma unroll
        for (int nt = 0; nt < 16; nt++) {
            o[nt][0] *= sc0; o[nt][1] *= sc0;
            o[nt][2] *= sc1; o[nt][3] *= sc1;
        }

        #pragma unroll
        for (int ks2 = 0; ks2 < 2; ks2++) {
            #pragma unroll
            for (int p8 = 0; p8 < 8; p8++) {
                uint32_t Bv[4];
                ldsm4(Bv, Vb + ((vb_off + (uint32_t)(p8 * 320 + ks2 * 8)) << 2));
                mma16(o[p8 * 2],     pA[ks2], Bv);
                mma16(o[p8 * 2 + 1], pA[ks2], Bv + 2);
            }
        }
    }

    float i0 = 1.0f / l0, i1 = 1.0f / l1;
    int row0 = wq * 16 + g, row1 = row0 + 8;
    #pragma unroll
    for (int nt = 0; nt < 16; nt++) {
        int col = nt * 8 + 2 * t;
        float2 lo = { o[nt][0] * i0, o[nt][1] * i0 };
        float2 hi = { o[nt][2] * i1, o[nt][3] * i1 };
        *(float2*)(Ob + (size_t)row0 * DH + col) = lo;
        *(float2*)(Ob + (size_t)row1 * DH + col) = hi;
    }
}

// ===========================================================================
extern "C" void kernel_launch(void* const* d_in, const int* in_sizes, int n_in,
                              void* d_out, int out_size)
{
    const float* q_in = (const float*)d_in[0];
    const float* k_in = (const float*)d_in[1];
    const float* v_in = (const float*)d_in[2];
    const float* Wq   = (const float*)d_in[3];
    const float* Wk   = (const float*)d_in[4];
    const float* Wv   = (const float*)d_in[5];
    const float* bq   = (const float*)d_in[6];
    const float* bk   = (const float*)d_in[7];
    const float* bv   = (const float*)d_in[8];
    float* out        = (float*)d_out;

    static bool attr_done = false;
    if (!attr_done) {
        cudaFuncSetAttribute(proj_kernel,  cudaFuncAttributeMaxDynamicSharedMemorySize, PJ_SMEM);
        cudaFuncSetAttribute(flash_kernel, cudaFuncAttributeMaxDynamicSharedMemorySize, FL_SMEM);
        attr_done = true;
    }

    wprep_kernel<<<dim3(64, 3), 256>>>(Wq, Wk, Wv);
    proj_kernel<<<dim3(MTOT / 128, 3), 256, PJ_SMEM>>>(q_in, k_in, v_in, bq, bk, bv);
    flash_kernel<<<dim3(SEQ / 64, NB), 128, FL_SMEM>>>(out);
}